// round 14
// baseline (speedup 1.0000x reference)
#include <cuda_runtime.h>
#include <cuda_fp16.h>
#include <math.h>
#include <stdint.h>

#define SEQ   512
#define BATCH 2048
#define HID   512
#define KC    1024
#define AKC   1536          // g_A row stride: [x0(512) | h_even(512) | h_odd(512)]
#define NBLK  148
#define NTHR  256
#define TILES 128           // 16 m-tiles x 8 h-tiles
#define STAGE 49152
#define OFF_A 0
#define OFF_B 16384
#define DYNSMEM (4*STAGE + 1024)
#define NRMAX 14

// ---------------- persistent device state (no allocs) ----------------
__device__ __align__(16) __half g_A [BATCH * AKC];    // fp16 activations
__device__ __align__(16) __half g_B [8 * 256 * KC];   // [hb][n'][k] fp16 weights
__device__ float g_bias[8 * 256];
__device__ float g_c[BATCH * HID];
__device__ float g_WiT[32 * HID];
__device__ float g_ypart[BATCH * 8];   // [b][hb] partial y dot products
__device__ unsigned g_cnt1[8 * 32];    // group counters (128B apart)
__device__ unsigned g_cnt2;
__device__ volatile unsigned g_bar_gen;

// ---------------- helpers ----------------
__device__ __forceinline__ uint32_t smaddr(const void* p) {
    return (uint32_t)__cvta_generic_to_shared(p);
}
__device__ __forceinline__ void cpasync16(uint32_t dst, const void* src) {
    asm volatile("cp.async.cg.shared.global [%0], [%1], 16;" :: "r"(dst), "l"(src));
}
__device__ __forceinline__ void cpasync4(uint32_t dst, const void* src) {
    asm volatile("cp.async.ca.shared.global [%0], [%1], 4;" :: "r"(dst), "l"(src));
}
__device__ __forceinline__ void cp_commit() {
    asm volatile("cp.async.commit_group;" ::: "memory");
}
__device__ __forceinline__ void cp_wait2() {
    asm volatile("cp.async.wait_group 2;" ::: "memory");
}
__device__ __forceinline__ void cp_wait1() {
    asm volatile("cp.async.wait_group 1;" ::: "memory");
}
__device__ __forceinline__ void cp_wait0() {
    asm volatile("cp.async.wait_group 0;" ::: "memory");
}
__device__ __forceinline__ void ldmx4(uint32_t* r, uint32_t addr) {
    asm volatile("ldmatrix.sync.aligned.m8n8.x4.shared.b16 {%0,%1,%2,%3}, [%4];"
                 : "=r"(r[0]), "=r"(r[1]), "=r"(r[2]), "=r"(r[3]) : "r"(addr));
}
__device__ __forceinline__ void mma16816(float* d, const uint32_t* a, const uint32_t* b) {
    asm volatile("mma.sync.aligned.m16n8k16.row.col.f32.f16.f16.f32 "
                 "{%0,%1,%2,%3}, {%4,%5,%6,%7}, {%8,%9}, {%0,%1,%2,%3};"
                 : "+f"(d[0]), "+f"(d[1]), "+f"(d[2]), "+f"(d[3])
                 : "r"(a[0]), "r"(a[1]), "r"(a[2]), "r"(a[3]), "r"(b[0]), "r"(b[1]));
}

// two-level grid barrier: 8 groups (18/19 CTAs) -> 8-wide root; pure spin
__device__ __forceinline__ void grid_sync() {
    __syncthreads();
    if (threadIdx.x == 0) {
        unsigned gen = g_bar_gen;
        __threadfence();
        const int grp = blockIdx.x & 7;
        const unsigned gsz = 18u + (grp < 4 ? 1u : 0u);
        if (atomicAdd(&g_cnt1[grp * 32], 1u) == gsz - 1u) {
            g_cnt1[grp * 32] = 0u;
            __threadfence();
            if (atomicAdd(&g_cnt2, 1u) == 7u) {
                g_cnt2 = 0u;
                __threadfence();
                g_bar_gen = gen + 1u;
            }
        }
        while (g_bar_gen == gen) { }
        __threadfence();
    }
    __syncthreads();
}

__device__ __forceinline__ float tanhap(float v) {
    float r;
    asm("tanh.approx.f32 %0, %1;" : "=f"(r) : "f"(v));
    return r;
}
__device__ __forceinline__ float sigap(float v) {
    return fmaf(0.5f, tanhap(0.5f * v), 0.5f);
}

// process order i=0..15 -> kb: h-half (8..15) first, then x0-half (0..7)
__device__ __forceinline__ int kb_of(int i) { return (i < 8) ? (8 + i) : (i - 8); }

// issue one k-slab (64 k) of A + B via cp.async into stage buffer.
__device__ __forceinline__ void issue_slab(uint32_t dstbase, int kb, int m0, int hb,
                                           int tid, int p) {
    const int ksrcA = kb * 64 + ((kb >= 8) ? p * 512 : 0);
    #pragma unroll
    for (int i = 0; i < 4; ++i) {
        int c = tid + i * NTHR;
        int row = c >> 3, kq = c & 7;
        size_t so = ((size_t)(m0 + row) * AKC + ksrcA + kq * 8) * 2;
        unsigned off = (unsigned)(row * 128) + (unsigned)((kq ^ (row & 7)) << 4);
        cpasync16(dstbase + OFF_A + off, (const char*)g_A + so);
    }
    #pragma unroll
    for (int i = 0; i < 8; ++i) {
        int c = tid + i * NTHR;
        int n = c >> 3, kq = c & 7;
        size_t so = (((size_t)hb * 256 + n) * KC + (size_t)kb * 64 + kq * 8) * 2;
        unsigned off = (unsigned)(n * 128) + (unsigned)((kq ^ (n & 7)) << 4);
        cpasync16(dstbase + OFF_B + off, (const char*)g_B + so);
    }
}

__global__ __launch_bounds__(NTHR, 1) void lstm_persist(
    const float* __restrict__ x,   const float* __restrict__ h0,
    const float* __restrict__ c0,  const float* __restrict__ y0,
    const float* __restrict__ W_in,  const float* __restrict__ b_in,
    const float* __restrict__ W_ih,  const float* __restrict__ W_hh,
    const float* __restrict__ b_ih,  const float* __restrict__ b_hh,
    const float* __restrict__ W_out, const float* __restrict__ b_out,
    float* __restrict__ out)
{
    extern __shared__ char dsm[];
    __shared__ float binS [HID];
    __shared__ float woutS[HID];
    __shared__ float biasS[256];
    __shared__ float inpS [NRMAX * 32];
    __shared__ float ypartS[128];

    const int tid  = threadIdx.x;
    const int bid  = blockIdx.x;
    const int warp = tid >> 5, lane = tid & 31;

    uint32_t raw = smaddr(dsm);
    uint32_t sb  = (raw + 1023u) & ~1023u;

    for (int i = tid; i < HID; i += NTHR) { binS[i] = b_in[i]; woutS[i] = W_out[i]; }
    if (tid < 128) ypartS[tid] = 0.f;

    // ---- one-time global init (striped across grid) ----
    for (int idx = bid * NTHR + tid; idx < 32 * HID; idx += NBLK * NTHR) {
        int j = idx >> 5, k = idx & 31;
        g_WiT[k * HID + j] = W_in[j * 32 + k];
    }
    for (int idx = bid * NTHR + tid; idx < 8 * 256 * KC; idx += NBLK * NTHR) {
        int hb = idx >> 18, rem = idx & 0x3FFFF;
        int n = rem >> 10, k = rem & 1023;
        int gate = n >> 6, j = n & 63;
        int srow = gate * 512 + hb * 64 + j;
        float w = (k < 512) ? W_ih[srow * 512 + k] : W_hh[srow * 512 + (k - 512)];
        g_B[idx] = __float2half_rn(w);
    }
    for (int idx = bid * NTHR + tid; idx < 8 * 256; idx += NBLK * NTHR) {
        int hb = idx >> 8, n = idx & 255;
        int gate = n >> 6, j = n & 63;
        int srow = gate * 512 + hb * 64 + j;
        g_bias[idx] = b_ih[srow] + b_hh[srow];
    }
    grid_sync();

    const int m0 = (bid & 15) * 128;
    const int hb = bid >> 4;
    if (bid < TILES) {
        for (int i = tid; i < 256; i += NTHR) biasS[i] = g_bias[hb * 256 + i];
    }

    const int b0 = (bid * BATCH) / NBLK;
    const int b1 = ((bid + 1) * BATCH) / NBLK;
    const int NR = b1 - b0;
    const float bout0 = b_out[0];

    // ---- MMA thread-geometry (8 warps, 64x64 warp tile) ----
    const int warp_m = warp & 1;
    const int warp_n = warp >> 1;
    const int l7 = lane & 7, q = lane >> 3;
    const int aRowL = warp_m * 64 + (q & 1) * 8 + l7;
    const int cA    = q >> 1;
    const int bRowL = warp_n * 16 + (q >> 1) * 8 + l7;
    const int cB    = q & 1;
    const int lq  = lane >> 2;
    const int lc2 = 2 * (lane & 3);
    const int jc  = tid * 2;             // x0 GEMM: thread owns cols jc, jc+1

    for (int t = 0; t <= SEQ; ++t) {
        const int p = t & 1;

        // ---- top: prefetch h slabs (t>0 MMA CTAs), then y per row ----
        if (t > 0 && t < SEQ && bid < TILES) {
            issue_slab(sb,             8, m0, hb, tid, p); cp_commit();
            issue_slab(sb + STAGE,     9, m0, hb, tid, p); cp_commit();
            issue_slab(sb + 2 * STAGE, 10, m0, hb, tid, p); cp_commit();
        }
        if (t == 0) {
            for (int b = b0 + warp; b < b1; b += 8) {
                for (int jj = lane; jj < HID; jj += 32) {
                    g_A[(size_t)b * AKC + 512 + jj] = __float2half_rn(h0[b * HID + jj]);
                    g_c[(size_t)b * HID + jj] = c0[b * HID + jj];
                }
            }
        }
        if (tid < NR) {
            const int b = b0 + tid;
            float yv;
            if (t == 0) {
                yv = y0[b];
            } else {
                float s = bout0;
                #pragma unroll
                for (int pp = 0; pp < 8; ++pp)
                    s += __ldcg(&g_ypart[(size_t)b * 8 + pp]);
                out[(size_t)(t - 1) * BATCH + b] = s;
                yv = s;
            }
            if (t < SEQ) inpS[tid * 32 + 31] = yv;
        }
        if (t == SEQ) break;

        if (t == 0 || bid >= TILES) {
            // ---- serial row phase (t==0 everywhere; non-MMA CTAs every step) ----
            __syncthreads();       // y visible before x-stage overwrite check
            for (int i = tid; i < NR * 31; i += NTHR) {
                int r = i / 31, cc = i - r * 31;
                inpS[r * 32 + cc] = __ldcg(&x[((size_t)t * BATCH + (b0 + r)) * 31 + cc]);
            }
            __syncthreads();
            for (int r = 0; r < NR; ++r) {
                float ax = binS[jc], ay = binS[jc + 1];
                #pragma unroll 8
                for (int k = 0; k < 32; ++k) {
                    const float a = inpS[r * 32 + k];
                    const float2 w = *(const float2*)(g_WiT + k * HID + jc);
                    ax = fmaf(a, w.x, ax); ay = fmaf(a, w.y, ay);
                }
                *(__half2*)(g_A + (size_t)(b0 + r) * AKC + jc) =
                    __floats2half2_rn(fmaxf(ax, 0.f), fmaxf(ay, 0.f));
            }
            grid_sync();   // syncM: x0 complete chip-wide
        }

        // ================= MMA PHASE =================
        if (bid < TILES) {
            float acc[4][8][4];
            #pragma unroll
            for (int mf = 0; mf < 4; ++mf)
                #pragma unroll
                for (int nf = 0; nf < 8; ++nf)
                    #pragma unroll
                    for (int e = 0; e < 4; ++e) acc[mf][nf][e] = 0.f;

            if (t == 0) {   // prefetch after syncM (h0 written by other CTAs)
                issue_slab(sb,             8, m0, hb, tid, p); cp_commit();
                issue_slab(sb + STAGE,     9, m0, hb, tid, p); cp_commit();
                issue_slab(sb + 2 * STAGE, 10, m0, hb, tid, p); cp_commit();
            }
            const bool ilv = (t > 0);   // interleave row work + mid-loop grid sync

            #pragma unroll
            for (int i = 0; i < 16; ++i) {
                if (i <= 13) cp_wait2(); else if (i == 14) cp_wait1(); else cp_wait0();
                __syncthreads();
                if (ilv && i == 5) grid_sync();   // syncM: x0 ready before kb=0 issue
                if (i + 3 < 16) {
                    if (i == 6 && t + 1 < SEQ) {
                        // x(t+1) smem prefetch (inpS x cols free after chunks)
                        for (int ii = tid; ii < NR * 31; ii += NTHR) {
                            int r = ii / 31, cc = ii - r * 31;
                            cpasync4(smaddr(&inpS[r * 32 + cc]),
                                     &x[((size_t)(t + 1) * BATCH + (b0 + r)) * 31 + cc]);
                        }
                    }
                    issue_slab(sb + (uint32_t)((i + 3) & 3) * STAGE, kb_of(i + 3),
                               m0, hb, tid, p);
                    cp_commit();
                }
                const uint32_t bufb = sb + (uint32_t)(i & 3) * STAGE;
                #pragma unroll
                for (int s4i = 0; s4i < 4; ++s4i) {
                    const int s4 = (s4i + warp_n) & 3;
                    uint32_t bh[4][4];
                    #pragma unroll
                    for (int g = 0; g < 4; ++g) {
                        uint32_t baddr = bufb + OFF_B
                            + (uint32_t)((bRowL + g * 64) * 128)
                            + (uint32_t)((((2 * s4 + cB) ^ l7)) << 4);
                        ldmx4(bh[g], baddr);
                    }
                    #pragma unroll
                    for (int mf = 0; mf < 4; ++mf) {
                        uint32_t ah[4];
                        uint32_t aaddr = bufb + OFF_A
                            + (uint32_t)((aRowL + mf * 16) * 128)
                            + (uint32_t)((((2 * s4 + cA) ^ l7)) << 4);
                        ldmx4(ah, aaddr);
                        #pragma unroll
                        for (int nf = 0; nf < 8; ++nf)
                            mma16816(acc[mf][nf], ah, &bh[nf >> 1][(nf & 1) * 2]);
                    }
                }
                // ---- interleaved x0 row-chunks (3 rows/iter, iters 0..4) ----
                if (ilv && i < 5) {
                    const int rlo = i * 3;
                    const int rhi = (rlo + 3 < NR) ? rlo + 3 : NR;
                    for (int r = rlo; r < rhi; ++r) {
                        float ax = binS[jc], ay = binS[jc + 1];
                        #pragma unroll 8
                        for (int k = 0; k < 32; ++k) {
                            const float a = inpS[r * 32 + k];
                            const float2 w = *(const float2*)(g_WiT + k * HID + jc);
                            ax = fmaf(a, w.x, ax); ay = fmaf(a, w.y, ay);
                        }
                        *(__half2*)(g_A + (size_t)(b0 + r) * AKC + jc) =
                            __floats2half2_rn(fmaxf(ax, 0.f), fmaxf(ay, 0.f));
                    }
                }
            }

            // ---- register-resident LSTM epilogue ----
            #pragma unroll
            for (int mf = 0; mf < 4; ++mf) {
                #pragma unroll
                for (int e2 = 0; e2 < 2; ++e2) {
                    const int r  = warp_m * 64 + mf * 16 + e2 * 8 + lq;
                    const int rg = m0 + r;
                    const int e0 = e2 * 2;
                    float yp = 0.f;
                    #pragma unroll
                    for (int sub = 0; sub < 2; ++sub) {
                        const int jl = warp_n * 16 + sub * 8 + lc2;
                        float I0 = sigap(acc[mf][0 + sub][e0]     + biasS[jl]);
                        float I1 = sigap(acc[mf][0 + sub][e0 + 1] + biasS[jl + 1]);
                        float F0 = sigap(acc[mf][2 + sub][e0]     + biasS[64 + jl]);
                        float F1 = sigap(acc[mf][2 + sub][e0 + 1] + biasS[64 + jl + 1]);
                        float G0 = tanhap(acc[mf][4 + sub][e0]     + biasS[128 + jl]);
                        float G1 = tanhap(acc[mf][4 + sub][e0 + 1] + biasS[128 + jl + 1]);
                        float O0 = sigap(acc[mf][6 + sub][e0]     + biasS[192 + jl]);
                        float O1 = sigap(acc[mf][6 + sub][e0 + 1] + biasS[192 + jl + 1]);
                        float* cp = g_c + (size_t)rg * HID + hb * 64 + jl;
                        float2 cv = *(float2*)cp;
                        float cn0 = F0 * cv.x + I0 * G0;
                        float cn1 = F1 * cv.y + I1 * G1;
                        *(float2*)cp = make_float2(cn0, cn1);
                        float h0f = O0 * tanhap(cn0);
                        float h1f = O1 * tanhap(cn1);
                        const float2 wv = *(const float2*)(woutS + hb * 64 + jl);
                        yp = fmaf(h0f, wv.x, fmaf(h1f, wv.y, yp));
                        *(__half2*)(g_A + (size_t)rg * AKC + 512 + (p ^ 1) * 512
                                    + hb * 64 + jl) = __floats2half2_rn(h0f, h1f);
                    }
                    yp += __shfl_xor_sync(0xffffffffu, yp, 1);
                    yp += __shfl_xor_sync(0xffffffffu, yp, 2);
                    if ((lane & 3) == 0) atomicAdd(&ypartS[r], yp);
                }
            }
            __syncthreads();
            if (tid < 128) {
                g_ypart[(size_t)(m0 + tid) * 8 + hb] = ypartS[tid];
                ypartS[tid] = 0.f;
            }
        }

        grid_sync();   // #2: h + ypart complete -> next step
    }
}

extern "C" void kernel_launch(void* const* d_in, const int* in_sizes, int n_in,
                              void* d_out, int out_size) {
    (void)in_sizes; (void)n_in; (void)out_size;
    const float* x     = (const float*)d_in[0];
    const float* h0    = (const float*)d_in[1];
    const float* c0    = (const float*)d_in[2];
    const float* y0    = (const float*)d_in[3];
    const float* W_in  = (const float*)d_in[4];
    const float* b_in  = (const float*)d_in[5];
    const float* W_ih  = (const float*)d_in[6];
    const float* W_hh  = (const float*)d_in[7];
    const float* b_ih  = (const float*)d_in[8];
    const float* b_hh  = (const float*)d_in[9];
    const float* W_out = (const float*)d_in[10];
    const float* b_out = (const float*)d_in[11];
    float* out = (float*)d_out;

    cudaFuncSetAttribute(lstm_persist, cudaFuncAttributeMaxDynamicSharedMemorySize, DYNSMEM);
    lstm_persist<<<NBLK, NTHR, DYNSMEM>>>(x, h0, c0, y0, W_in, b_in, W_ih, W_hh,
                                          b_ih, b_hh, W_out, b_out, out);
}

// round 15
// speedup vs baseline: 1.1067x; 1.1067x over previous
#include <cuda_runtime.h>
#include <cuda_fp16.h>
#include <math.h>
#include <stdint.h>

#define SEQ   512
#define BATCH 2048
#define HID   512
#define KC    1024
#define AKC   1536          // g_A row stride: [x0(512) | h_even(512) | h_odd(512)]
#define NBLK  148
#define NTHR  256
#define TILES 128           // 16 m-tiles x 8 h-tiles
#define STAGE 49152
#define OFF_A 0
#define OFF_B 16384
#define DYNSMEM (4*STAGE + 1024)
#define NRMAX 14

// ---------------- persistent device state (no allocs) ----------------
__device__ __align__(16) __half g_A [BATCH * AKC];    // fp16 activations
__device__ __align__(16) __half g_B [8 * 256 * KC];   // [hb][n'][k] fp16 weights
__device__ float g_bias[8 * 256];
__device__ float g_c[BATCH * HID];
__device__ float g_WiT[32 * HID];
__device__ float g_ypart[BATCH * 8];   // [b][hb] partial y dot products
__device__ unsigned g_cnt1[8 * 32];    // barrier group counters (128B apart)
__device__ unsigned g_cnt2;
__device__ volatile unsigned g_bar_gen;
__device__ unsigned g_x0c[16 * 32];    // per-m-tile x0 producer counters
__device__ unsigned g_hc [16 * 32];    // per-m-tile epilogue (h/ypart) counters

// ---------------- helpers ----------------
__device__ __forceinline__ uint32_t smaddr(const void* p) {
    return (uint32_t)__cvta_generic_to_shared(p);
}
__device__ __forceinline__ void cpasync16(uint32_t dst, const void* src) {
    asm volatile("cp.async.cg.shared.global [%0], [%1], 16;" :: "r"(dst), "l"(src));
}
__device__ __forceinline__ void cpasync4(uint32_t dst, const void* src) {
    asm volatile("cp.async.ca.shared.global [%0], [%1], 4;" :: "r"(dst), "l"(src));
}
__device__ __forceinline__ void cp_commit() {
    asm volatile("cp.async.commit_group;" ::: "memory");
}
__device__ __forceinline__ void cp_wait2() {
    asm volatile("cp.async.wait_group 2;" ::: "memory");
}
__device__ __forceinline__ void cp_wait1() {
    asm volatile("cp.async.wait_group 1;" ::: "memory");
}
__device__ __forceinline__ void cp_wait0() {
    asm volatile("cp.async.wait_group 0;" ::: "memory");
}
__device__ __forceinline__ void ldmx4(uint32_t* r, uint32_t addr) {
    asm volatile("ldmatrix.sync.aligned.m8n8.x4.shared.b16 {%0,%1,%2,%3}, [%4];"
                 : "=r"(r[0]), "=r"(r[1]), "=r"(r[2]), "=r"(r[3]) : "r"(addr));
}
__device__ __forceinline__ void mma16816(float* d, const uint32_t* a, const uint32_t* b) {
    asm volatile("mma.sync.aligned.m16n8k16.row.col.f32.f16.f16.f32 "
                 "{%0,%1,%2,%3}, {%4,%5,%6,%7}, {%8,%9}, {%0,%1,%2,%3};"
                 : "+f"(d[0]), "+f"(d[1]), "+f"(d[2]), "+f"(d[3])
                 : "r"(a[0]), "r"(a[1]), "r"(a[2]), "r"(a[3]), "r"(b[0]), "r"(b[1]));
}

// global barrier (init + t==0 only): 8 groups -> 8-wide root; pure spin
__device__ __forceinline__ void grid_sync() {
    __syncthreads();
    if (threadIdx.x == 0) {
        unsigned gen = g_bar_gen;
        __threadfence();
        const int grp = blockIdx.x & 7;
        const unsigned gsz = 18u + (grp < 4 ? 1u : 0u);
        if (atomicAdd(&g_cnt1[grp * 32], 1u) == gsz - 1u) {
            g_cnt1[grp * 32] = 0u;
            __threadfence();
            if (atomicAdd(&g_cnt2, 1u) == 7u) {
                g_cnt2 = 0u;
                __threadfence();
                g_bar_gen = gen + 1u;
            }
        }
        while (g_bar_gen == gen) { }
        __threadfence();
    }
    __syncthreads();
}

__device__ __forceinline__ float tanhap(float v) {
    float r;
    asm("tanh.approx.f32 %0, %1;" : "=f"(r) : "f"(v));
    return r;
}
__device__ __forceinline__ float sigap(float v) {
    return fmaf(0.5f, tanhap(0.5f * v), 0.5f);
}

// process order i=0..15 -> kb: h-half (8..15) first, then x0-half (0..7)
__device__ __forceinline__ int kb_of(int i) { return (i < 8) ? (8 + i) : (i - 8); }

// issue one k-slab (64 k) of A + B via cp.async into stage buffer.
__device__ __forceinline__ void issue_slab(uint32_t dstbase, int kb, int m0, int hb,
                                           int tid, int p) {
    const int ksrcA = kb * 64 + ((kb >= 8) ? p * 512 : 0);
    #pragma unroll
    for (int i = 0; i < 4; ++i) {
        int c = tid + i * NTHR;
        int row = c >> 3, kq = c & 7;
        size_t so = ((size_t)(m0 + row) * AKC + ksrcA + kq * 8) * 2;
        unsigned off = (unsigned)(row * 128) + (unsigned)((kq ^ (row & 7)) << 4);
        cpasync16(dstbase + OFF_A + off, (const char*)g_A + so);
    }
    #pragma unroll
    for (int i = 0; i < 8; ++i) {
        int c = tid + i * NTHR;
        int n = c >> 3, kq = c & 7;
        size_t so = (((size_t)hb * 256 + n) * KC + (size_t)kb * 64 + kq * 8) * 2;
        unsigned off = (unsigned)(n * 128) + (unsigned)((kq ^ (n & 7)) << 4);
        cpasync16(dstbase + OFF_B + off, (const char*)g_B + so);
    }
}

__global__ __launch_bounds__(NTHR, 1) void lstm_persist(
    const float* __restrict__ x,   const float* __restrict__ h0,
    const float* __restrict__ c0,  const float* __restrict__ y0,
    const float* __restrict__ W_in,  const float* __restrict__ b_in,
    const float* __restrict__ W_ih,  const float* __restrict__ W_hh,
    const float* __restrict__ b_ih,  const float* __restrict__ b_hh,
    const float* __restrict__ W_out, const float* __restrict__ b_out,
    float* __restrict__ out)
{
    extern __shared__ char dsm[];
    __shared__ float binS [HID];
    __shared__ float woutS[HID];
    __shared__ float biasS[256];
    __shared__ float inpS [NRMAX * 32];
    __shared__ float ypartS[128];

    const int tid  = threadIdx.x;
    const int bid  = blockIdx.x;
    const int warp = tid >> 5, lane = tid & 31;

    uint32_t raw = smaddr(dsm);
    uint32_t sb  = (raw + 1023u) & ~1023u;

    for (int i = tid; i < HID; i += NTHR) { binS[i] = b_in[i]; woutS[i] = W_out[i]; }
    if (tid < 128) ypartS[tid] = 0.f;

    // ---- zero dataflow counters (graph replays reuse device globals!) ----
    if (bid == 0 && tid < 16) { g_x0c[tid * 32] = 0u; g_hc[tid * 32] = 0u; }

    // ---- one-time global init (striped across grid) ----
    for (int idx = bid * NTHR + tid; idx < 32 * HID; idx += NBLK * NTHR) {
        int j = idx >> 5, k = idx & 31;
        g_WiT[k * HID + j] = W_in[j * 32 + k];
    }
    for (int idx = bid * NTHR + tid; idx < 8 * 256 * KC; idx += NBLK * NTHR) {
        int hb = idx >> 18, rem = idx & 0x3FFFF;
        int n = rem >> 10, k = rem & 1023;
        int gate = n >> 6, j = n & 63;
        int srow = gate * 512 + hb * 64 + j;
        float w = (k < 512) ? W_ih[srow * 512 + k] : W_hh[srow * 512 + (k - 512)];
        g_B[idx] = __float2half_rn(w);
    }
    for (int idx = bid * NTHR + tid; idx < 8 * 256; idx += NBLK * NTHR) {
        int hb = idx >> 8, n = idx & 255;
        int gate = n >> 6, j = n & 63;
        int srow = gate * 512 + hb * 64 + j;
        g_bias[idx] = b_ih[srow] + b_hh[srow];
    }
    grid_sync();

    const int m0 = (bid & 15) * 128;
    const int hb = bid >> 4;
    const int mytile = bid & 15;
    if (bid < TILES) {
        for (int i = tid; i < 256; i += NTHR) biasS[i] = g_bias[hb * 256 + i];
    }

    const int b0 = (bid * BATCH) / NBLK;
    const int b1 = ((bid + 1) * BATCH) / NBLK;
    const int NR = b1 - b0;
    const float bout0 = b_out[0];
    const int jlo = b0 >> 7, jhi = (b1 - 1) >> 7;
    int Pmt = 0;   // number of row-CTAs producing x0 rows of mytile
    for (int c = 0; c < NBLK; ++c) {
        int rb0 = c * BATCH / NBLK, rb1 = (c + 1) * BATCH / NBLK;
        if (rb0 < (mytile + 1) * 128 && rb1 > mytile * 128) Pmt++;
    }

    // ---- MMA thread-geometry (8 warps, 64x64 warp tile) ----
    const int warp_m = warp & 1;
    const int warp_n = warp >> 1;
    const int l7 = lane & 7, q = lane >> 3;
    const int aRowL = warp_m * 64 + (q & 1) * 8 + l7;
    const int cA    = q >> 1;
    const int bRowL = warp_n * 16 + (q >> 1) * 8 + l7;
    const int cB    = q & 1;
    const int lq  = lane >> 2;
    const int lc2 = 2 * (lane & 3);
    const int jc  = tid * 2;

    for (int t = 0; t <= SEQ; ++t) {
        const int p = t & 1;

        // ---- fine-grained wait: h(t)/ypart(t) of needed m-tiles ----
        if (t > 0) {
            if (tid == 0) {
                const unsigned tgt = 8u * (unsigned)t;
                if (bid < TILES)
                    while (*(volatile unsigned*)&g_hc[mytile * 32] < tgt) { }
                for (int j = jlo; j <= jhi; ++j)
                    while (*(volatile unsigned*)&g_hc[j * 32] < tgt) { }
                __threadfence();
            }
            __syncthreads();
        }
        // ---- prefetch first three h-half slabs (now safe) ----
        if (t > 0 && t < SEQ && bid < TILES) {
            issue_slab(sb,             8, m0, hb, tid, p); cp_commit();
            issue_slab(sb + STAGE,     9, m0, hb, tid, p); cp_commit();
            issue_slab(sb + 2 * STAGE, 10, m0, hb, tid, p); cp_commit();
        }
        if (t == 0) {
            for (int b = b0 + warp; b < b1; b += 8) {
                for (int jj = lane; jj < HID; jj += 32) {
                    g_A[(size_t)b * AKC + 512 + jj] = __float2half_rn(h0[b * HID + jj]);
                    g_c[(size_t)b * HID + jj] = c0[b * HID + jj];
                }
            }
        }
        // ---- y per row (sum of 8 epilogue partials), write out ----
        if (tid < NR) {
            const int b = b0 + tid;
            float yv;
            if (t == 0) {
                yv = y0[b];
            } else {
                float s = bout0;
                #pragma unroll
                for (int pp = 0; pp < 8; ++pp)
                    s += __ldcg(&g_ypart[(size_t)b * 8 + pp]);
                out[(size_t)(t - 1) * BATCH + b] = s;
                yv = s;
            }
            if (t < SEQ) inpS[tid * 32 + 31] = yv;
        }
        if (t == SEQ) break;

        // ---- stage x (MMA CTAs at t>0 use smem-prefetched x) ----
        if (t == 0 || bid >= TILES) {
            for (int i = tid; i < NR * 31; i += NTHR) {
                int r = i / 31, cc = i - r * 31;
                inpS[r * 32 + cc] = __ldcg(&x[((size_t)t * BATCH + (b0 + r)) * 31 + cc]);
            }
        }
        __syncthreads();

        // ---- x0 GEMM: thread owns cols jc..jc+1, all NR rows ----
        for (int r = 0; r < NR; ++r) {
            float ax = binS[jc], ay = binS[jc + 1];
            #pragma unroll 8
            for (int k = 0; k < 32; ++k) {
                const float a = inpS[r * 32 + k];
                const float2 w = *(const float2*)(g_WiT + k * HID + jc);
                ax = fmaf(a, w.x, ax); ay = fmaf(a, w.y, ay);
            }
            *(__half2*)(g_A + (size_t)(b0 + r) * AKC + jc) =
                __floats2half2_rn(fmaxf(ax, 0.f), fmaxf(ay, 0.f));
        }
        __syncthreads();
        if (tid == 0) {
            __threadfence();
            for (int j = jlo; j <= jhi; ++j) atomicAdd(&g_x0c[j * 32], 1u);
        }
        if (t == 0) grid_sync();   // h0/c0 staged chip-wide (once)

        // ================= MMA PHASE =================
        if (bid < TILES) {
            float acc[4][8][4];
            #pragma unroll
            for (int mf = 0; mf < 4; ++mf)
                #pragma unroll
                for (int nf = 0; nf < 8; ++nf)
                    #pragma unroll
                    for (int e = 0; e < 4; ++e) acc[mf][nf][e] = 0.f;

            if (t == 0) {   // prefetch after the global sync at t==0
                issue_slab(sb,             8, m0, hb, tid, p); cp_commit();
                issue_slab(sb + STAGE,     9, m0, hb, tid, p); cp_commit();
                issue_slab(sb + 2 * STAGE, 10, m0, hb, tid, p); cp_commit();
            }

            #pragma unroll
            for (int i = 0; i < 16; ++i) {
                if (i <= 13) cp_wait2(); else if (i == 14) cp_wait1(); else cp_wait0();
                __syncthreads();
                if (i == 5) {   // x0 of mytile must exist before kb=0 issue below
                    if (tid == 0) {
                        const unsigned tgt = (unsigned)Pmt * (unsigned)(t + 1);
                        while (*(volatile unsigned*)&g_x0c[mytile * 32] < tgt) { }
                        __threadfence();
                    }
                    __syncthreads();
                }
                if (i + 3 < 16) {
                    if (i == 0 && t + 1 < SEQ) {
                        // piggyback x(t+1) smem prefetch on this commit group
                        for (int ii = tid; ii < NR * 31; ii += NTHR) {
                            int r = ii / 31, cc = ii - r * 31;
                            cpasync4(smaddr(&inpS[r * 32 + cc]),
                                     &x[((size_t)(t + 1) * BATCH + (b0 + r)) * 31 + cc]);
                        }
                    }
                    issue_slab(sb + (uint32_t)((i + 3) & 3) * STAGE, kb_of(i + 3),
                               m0, hb, tid, p);
                    cp_commit();
                }
                const uint32_t bufb = sb + (uint32_t)(i & 3) * STAGE;
                #pragma unroll
                for (int s4i = 0; s4i < 4; ++s4i) {
                    const int s4 = (s4i + warp_n) & 3;
                    uint32_t bh[4][4];
                    #pragma unroll
                    for (int g = 0; g < 4; ++g) {
                        uint32_t baddr = bufb + OFF_B
                            + (uint32_t)((bRowL + g * 64) * 128)
                            + (uint32_t)((((2 * s4 + cB) ^ l7)) << 4);
                        ldmx4(bh[g], baddr);
                    }
                    #pragma unroll
                    for (int mf = 0; mf < 4; ++mf) {
                        uint32_t ah[4];
                        uint32_t aaddr = bufb + OFF_A
                            + (uint32_t)((aRowL + mf * 16) * 128)
                            + (uint32_t)((((2 * s4 + cA) ^ l7)) << 4);
                        ldmx4(ah, aaddr);
                        #pragma unroll
                        for (int nf = 0; nf < 8; ++nf)
                            mma16816(acc[mf][nf], ah, &bh[nf >> 1][(nf & 1) * 2]);
                    }
                }
            }

            // ---- register-resident LSTM epilogue ----
            #pragma unroll
            for (int mf = 0; mf < 4; ++mf) {
                #pragma unroll
                for (int e2 = 0; e2 < 2; ++e2) {
                    const int r  = warp_m * 64 + mf * 16 + e2 * 8 + lq;
                    const int rg = m0 + r;
                    const int e0 = e2 * 2;
                    float yp = 0.f;
                    #pragma unroll
                    for (int sub = 0; sub < 2; ++sub) {
                        const int jl = warp_n * 16 + sub * 8 + lc2;
                        float I0 = sigap(acc[mf][0 + sub][e0]     + biasS[jl]);
                        float I1 = sigap(acc[mf][0 + sub][e0 + 1] + biasS[jl + 1]);
                        float F0 = sigap(acc[mf][2 + sub][e0]     + biasS[64 + jl]);
                        float F1 = sigap(acc[mf][2 + sub][e0 + 1] + biasS[64 + jl + 1]);
                        float G0 = tanhap(acc[mf][4 + sub][e0]     + biasS[128 + jl]);
                        float G1 = tanhap(acc[mf][4 + sub][e0 + 1] + biasS[128 + jl + 1]);
                        float O0 = sigap(acc[mf][6 + sub][e0]     + biasS[192 + jl]);
                        float O1 = sigap(acc[mf][6 + sub][e0 + 1] + biasS[192 + jl + 1]);
                        float* cp = g_c + (size_t)rg * HID + hb * 64 + jl;
                        float2 cv = *(float2*)cp;
                        float cn0 = F0 * cv.x + I0 * G0;
                        float cn1 = F1 * cv.y + I1 * G1;
                        *(float2*)cp = make_float2(cn0, cn1);
                        float h0f = O0 * tanhap(cn0);
                        float h1f = O1 * tanhap(cn1);
                        const float2 wv = *(const float2*)(woutS + hb * 64 + jl);
                        yp = fmaf(h0f, wv.x, fmaf(h1f, wv.y, yp));
                        *(__half2*)(g_A + (size_t)rg * AKC + 512 + (p ^ 1) * 512
                                    + hb * 64 + jl) = __floats2half2_rn(h0f, h1f);
                    }
                    yp += __shfl_xor_sync(0xffffffffu, yp, 1);
                    yp += __shfl_xor_sync(0xffffffffu, yp, 2);
                    if ((lane & 3) == 0) atomicAdd(&ypartS[r], yp);
                }
            }
            __syncthreads();
            if (tid < 128) {
                g_ypart[(size_t)(m0 + tid) * 8 + hb] = ypartS[tid];
                ypartS[tid] = 0.f;
            }
            __syncthreads();
            if (tid == 0) {
                __threadfence();
                atomicAdd(&g_hc[mytile * 32], 1u);   // h(t+1)+ypart(t+1) published
            }
        }
        // NO global barrier here — dataflow counters carry the dependency
    }
}

extern "C" void kernel_launch(void* const* d_in, const int* in_sizes, int n_in,
                              void* d_out, int out_size) {
    (void)in_sizes; (void)n_in; (void)out_size;
    const float* x     = (const float*)d_in[0];
    const float* h0    = (const float*)d_in[1];
    const float* c0    = (const float*)d_in[2];
    const float* y0    = (const float*)d_in[3];
    const float* W_in  = (const float*)d_in[4];
    const float* b_in  = (const float*)d_in[5];
    const float* W_ih  = (const float*)d_in[6];
    const float* W_hh  = (const float*)d_in[7];
    const float* b_ih  = (const float*)d_in[8];
    const float* b_hh  = (const float*)d_in[9];
    const float* W_out = (const float*)d_in[10];
    const float* b_out = (const float*)d_in[11];
    float* out = (float*)d_out;

    cudaFuncSetAttribute(lstm_persist, cudaFuncAttributeMaxDynamicSharedMemorySize, DYNSMEM);
    lstm_persist<<<NBLK, NTHR, DYNSMEM>>>(x, h0, c0, y0, W_in, b_in, W_ih, W_hh,
                                          b_ih, b_hh, W_out, b_out, out);
}

// round 17
// speedup vs baseline: 1.2294x; 1.1108x over previous
#include <cuda_runtime.h>
#include <cuda_fp16.h>
#include <math.h>
#include <stdint.h>

#define SEQ   512
#define BATCH 2048
#define HID   512
#define KC    1024
#define AKC   1536          // g_A row stride: [x0(512) | h_even(512) | h_odd(512)]
#define NBLK  148
#define NTHR  256
#define TILES 128           // 16 m-tiles x 8 h-tiles
#define STAGE 16384         // A-only slab (128 rows x 64 k x fp16)
#define DYNSMEM (4*STAGE + 1024)
#define NRMAX 14

// ---------------- persistent device state (no allocs) ----------------
__device__ __align__(16) __half g_A [BATCH * AKC];    // fp16 activations
// B pre-packed in mma-fragment order:
// [hb][kb][s4][gate][warp_n][lane][8 halves]  (16B per lane chunk)
__device__ __align__(16) __half g_Bf[8 * 16 * 4 * 4 * 4 * 32 * 8];   // 4 MB
__device__ float g_bias[8 * 256];
__device__ float g_c[BATCH * HID];
__device__ float g_WiT[32 * HID];
__device__ float g_ypart[BATCH * 8];   // [b][hb] partial y dot products
__device__ unsigned g_cnt1[8 * 32];    // barrier group counters (128B apart)
__device__ unsigned g_cnt2;
__device__ volatile unsigned g_bar_gen;

// ---------------- helpers ----------------
__device__ __forceinline__ uint32_t smaddr(const void* p) {
    return (uint32_t)__cvta_generic_to_shared(p);
}
__device__ __forceinline__ void cpasync16(uint32_t dst, const void* src) {
    asm volatile("cp.async.cg.shared.global [%0], [%1], 16;" :: "r"(dst), "l"(src));
}
__device__ __forceinline__ void cpasync4(uint32_t dst, const void* src) {
    asm volatile("cp.async.ca.shared.global [%0], [%1], 4;" :: "r"(dst), "l"(src));
}
__device__ __forceinline__ void cp_commit() {
    asm volatile("cp.async.commit_group;" ::: "memory");
}
__device__ __forceinline__ void cp_wait2() {
    asm volatile("cp.async.wait_group 2;" ::: "memory");
}
__device__ __forceinline__ void cp_wait1() {
    asm volatile("cp.async.wait_group 1;" ::: "memory");
}
__device__ __forceinline__ void cp_wait0() {
    asm volatile("cp.async.wait_group 0;" ::: "memory");
}
__device__ __forceinline__ void ldmx4(uint32_t* r, uint32_t addr) {
    asm volatile("ldmatrix.sync.aligned.m8n8.x4.shared.b16 {%0,%1,%2,%3}, [%4];"
                 : "=r"(r[0]), "=r"(r[1]), "=r"(r[2]), "=r"(r[3]) : "r"(addr));
}
__device__ __forceinline__ void mma16816(float* d, const uint32_t* a, const uint32_t* b) {
    asm volatile("mma.sync.aligned.m16n8k16.row.col.f32.f16.f16.f32 "
                 "{%0,%1,%2,%3}, {%4,%5,%6,%7}, {%8,%9}, {%0,%1,%2,%3};"
                 : "+f"(d[0]), "+f"(d[1]), "+f"(d[2]), "+f"(d[3])
                 : "r"(a[0]), "r"(a[1]), "r"(a[2]), "r"(a[3]), "r"(b[0]), "r"(b[1]));
}

// two-level grid barrier: 8 groups (18/19 CTAs) -> 8-wide root; pure spin
__device__ __forceinline__ void grid_sync() {
    __syncthreads();
    if (threadIdx.x == 0) {
        unsigned gen = g_bar_gen;
        __threadfence();
        const int grp = blockIdx.x & 7;
        const unsigned gsz = 18u + (grp < 4 ? 1u : 0u);
        if (atomicAdd(&g_cnt1[grp * 32], 1u) == gsz - 1u) {
            g_cnt1[grp * 32] = 0u;
            __threadfence();
            if (atomicAdd(&g_cnt2, 1u) == 7u) {
                g_cnt2 = 0u;
                __threadfence();
                g_bar_gen = gen + 1u;
            }
        }
        while (g_bar_gen == gen) { }
        __threadfence();
    }
    __syncthreads();
}

__device__ __forceinline__ float tanhap(float v) {
    float r;
    asm("tanh.approx.f32 %0, %1;" : "=f"(r) : "f"(v));
    return r;
}
__device__ __forceinline__ float sigap(float v) {
    return fmaf(0.5f, tanhap(0.5f * v), 0.5f);
}

// process order i=0..15 -> kb: h-half (8..15) first, then x0-half (0..7)
__device__ __forceinline__ int kb_of(int i) { return (i < 8) ? (8 + i) : (i - 8); }

// issue one A k-slab (64 k) via cp.async into stage buffer.
__device__ __forceinline__ void issue_slab(uint32_t dstbase, int kb, int m0,
                                           int tid, int p) {
    const int ksrcA = kb * 64 + ((kb >= 8) ? p * 512 : 0);
    #pragma unroll
    for (int i = 0; i < 4; ++i) {
        int c = tid + i * NTHR;
        int row = c >> 3, kq = c & 7;
        size_t so = ((size_t)(m0 + row) * AKC + ksrcA + kq * 8) * 2;
        unsigned off = (unsigned)(row * 128) + (unsigned)((kq ^ (row & 7)) << 4);
        cpasync16(dstbase + off, (const char*)g_A + so);
    }
}

// load one s4-step of B fragments (4 gates) straight into registers
#define LOADB(dst, kbv, s4v) do {                                          \
    const char* _p = bfb + (kbv) * 32768 + (s4v) * 8192;                   \
    (dst)[0] = *(const uint4*)(_p);                                        \
    (dst)[1] = *(const uint4*)(_p + 2048);                                 \
    (dst)[2] = *(const uint4*)(_p + 4096);                                 \
    (dst)[3] = *(const uint4*)(_p + 6144);                                 \
} while (0)

__global__ __launch_bounds__(NTHR, 1) void lstm_persist(
    const float* __restrict__ x,   const float* __restrict__ h0,
    const float* __restrict__ c0,  const float* __restrict__ y0,
    const float* __restrict__ W_in,  const float* __restrict__ b_in,
    const float* __restrict__ W_ih,  const float* __restrict__ W_hh,
    const float* __restrict__ b_ih,  const float* __restrict__ b_hh,
    const float* __restrict__ W_out, const float* __restrict__ b_out,
    float* __restrict__ out)
{
    extern __shared__ char dsm[];
    __shared__ float binS [HID];
    __shared__ float woutS[HID];
    __shared__ float biasS[256];
    __shared__ float inpS [NRMAX * 32];
    __shared__ float ypartS[128];

    const int tid  = threadIdx.x;
    const int bid  = blockIdx.x;
    const int warp = tid >> 5, lane = tid & 31;

    uint32_t raw = smaddr(dsm);
    uint32_t sb  = (raw + 1023u) & ~1023u;

    for (int i = tid; i < HID; i += NTHR) { binS[i] = b_in[i]; woutS[i] = W_out[i]; }
    if (tid < 128) ypartS[tid] = 0.f;

    // ---- one-time global init (striped across grid) ----
    for (int idx = bid * NTHR + tid; idx < 32 * HID; idx += NBLK * NTHR) {
        int j = idx >> 5, k = idx & 31;
        g_WiT[k * HID + j] = W_in[j * 32 + k];
    }
    // B packed in fragment order: word idx -> (hb,kb,s4,g,wn,lane,w)
    for (int idx = bid * NTHR + tid; idx < 8 * 16 * 4 * 4 * 4 * 32 * 4;
         idx += NBLK * NTHR) {
        int w = idx & 3;  int chunk = idx >> 2;
        int ln = chunk & 31;  int tmp = chunk >> 5;
        int wn = tmp & 3;  tmp >>= 2;
        int g  = tmp & 3;  tmp >>= 2;
        int s4 = tmp & 3;  tmp >>= 2;
        int kb = tmp & 15; int hb = tmp >> 4;
        int j  = w >> 1, rr = w & 1;                 // n-subblock, k+8 select
        int kg = kb * 64 + s4 * 16 + 2 * (ln & 3) + rr * 8;
        int jcol = wn * 16 + j * 8 + (ln >> 2);      // col within 64-wide gate blk
        int srow = g * 512 + hb * 64 + jcol;
        float w0 = (kg < 512) ? W_ih[srow * 512 + kg] : W_hh[srow * 512 + kg - 512];
        float w1 = (kg + 1 < 512) ? W_ih[srow * 512 + kg + 1]
                                  : W_hh[srow * 512 + kg + 1 - 512];
        ((__half2*)g_Bf)[idx] = __floats2half2_rn(w0, w1);
    }
    for (int idx = bid * NTHR + tid; idx < 8 * 256; idx += NBLK * NTHR) {
        int hb = idx >> 8, n = idx & 255;
        int gate = n >> 6, j = n & 63;
        int srow = gate * 512 + hb * 64 + j;
        g_bias[idx] = b_ih[srow] + b_hh[srow];
    }
    grid_sync();

    const int m0 = (bid & 15) * 128;
    const int hb = bid >> 4;
    if (bid < TILES) {
        for (int i = tid; i < 256; i += NTHR) biasS[i] = g_bias[hb * 256 + i];
    }

    const int b0 = (bid * BATCH) / NBLK;
    const int b1 = ((bid + 1) * BATCH) / NBLK;
    const int NR = b1 - b0;
    const float bout0 = b_out[0];

    // ---- MMA thread-geometry (8 warps, 64x64 warp tile) ----
    const int warp_m = warp & 1;
    const int warp_n = warp >> 1;
    const int l7 = lane & 7, q = lane >> 3;
    const int aRowL = warp_m * 64 + (q & 1) * 8 + l7;
    const int cA    = q >> 1;
    const int lq  = lane >> 2;
    const int lc2 = 2 * (lane & 3);
    // per-thread base into fragment-packed B
    const char* bfb = (const char*)g_Bf + (size_t)hb * 524288
                    + warp_n * 512 + lane * 16;

    for (int t = 0; t <= SEQ; ++t) {
        const int p = t & 1;

        // ---- top: prefetch h slabs (t>0 MMA CTAs), then y per row ----
        if (t > 0 && t < SEQ && bid < TILES) {
            issue_slab(sb,             8, m0, tid, p); cp_commit();
            issue_slab(sb + STAGE,     9, m0, tid, p); cp_commit();
            issue_slab(sb + 2 * STAGE, 10, m0, tid, p); cp_commit();
        }
        if (t == 0) {
            for (int b = b0 + warp; b < b1; b += 8) {
                for (int jj = lane; jj < HID; jj += 32) {
                    g_A[(size_t)b * AKC + 512 + jj] = __float2half_rn(h0[b * HID + jj]);
                    g_c[(size_t)b * HID + jj] = c0[b * HID + jj];
                }
            }
        }
        if (tid < NR) {
            const int b = b0 + tid;
            float yv;
            if (t == 0) {
                yv = y0[b];
            } else {
                float s = bout0;
                #pragma unroll
                for (int pp = 0; pp < 8; ++pp)
                    s += __ldcg(&g_ypart[(size_t)b * 8 + pp]);
                out[(size_t)(t - 1) * BATCH + b] = s;
                yv = s;
            }
            if (t < SEQ) inpS[tid * 32 + 31] = yv;
        }
        if (t == SEQ) break;

        // ---- stage x (MMA CTAs at t>0 use smem-prefetched x) ----
        if (t == 0 || bid >= TILES) {
            for (int i = tid; i < NR * 31; i += NTHR) {
                int r = i / 31, cc = i - r * 31;
                inpS[r * 32 + cc] = __ldcg(&x[((size_t)t * BATCH + (b0 + r)) * 31 + cc]);
            }
        }
        __syncthreads();

        // ---- col-block x0 GEMM: warp owns 64 cols, lane owns 2, all NR rows ----
        {
            const int jc = warp * 64 + lane * 2;
            const float2 bb = *(const float2*)(binS + jc);
            float2 ac[NRMAX];
            #pragma unroll
            for (int r = 0; r < NRMAX; ++r) ac[r] = bb;
            #pragma unroll 4
            for (int k = 0; k < 32; ++k) {
                const float2 w = *(const float2*)(g_WiT + k * HID + jc);
                #pragma unroll
                for (int r = 0; r < NRMAX; ++r) {
                    if (r < NR) {
                        const float a = inpS[r * 32 + k];
                        ac[r].x = fmaf(a, w.x, ac[r].x);
                        ac[r].y = fmaf(a, w.y, ac[r].y);
                    }
                }
            }
            #pragma unroll
            for (int r = 0; r < NRMAX; ++r) {
                if (r < NR) {
                    float vx = fmaxf(ac[r].x, 0.f), vy = fmaxf(ac[r].y, 0.f);
                    *(__half2*)(g_A + (size_t)(b0 + r) * AKC + jc) =
                        __floats2half2_rn(vx, vy);
                }
            }
        }

        grid_sync();   // A complete -> GEMM may read

        // ================= MMA PHASE (fp16 mma.sync; B direct from global) ======
        if (bid < TILES) {
            float acc[4][8][4];
            #pragma unroll
            for (int mf = 0; mf < 4; ++mf)
                #pragma unroll
                for (int nf = 0; nf < 8; ++nf)
                    #pragma unroll
                    for (int e = 0; e < 4; ++e) acc[mf][nf][e] = 0.f;

            if (t == 0) {   // no prefetch happened during row phase at t==0
                issue_slab(sb,             8, m0, tid, p); cp_commit();
                issue_slab(sb + STAGE,     9, m0, tid, p); cp_commit();
                issue_slab(sb + 2 * STAGE, 10, m0, tid, p); cp_commit();
            }

            // B register double-buffer, one s4-step ahead
            uint4 bh[2][4];
            LOADB(bh[0], 8 /*kb_of(0)*/, (warp_n & 3));

            for (int i = 0; i < 16; ++i) {
                if (i <= 13) cp_wait2(); else if (i == 14) cp_wait1(); else cp_wait0();
                __syncthreads();
                if (i + 3 < 16) {
                    if (i == 0 && t + 1 < SEQ) {
                        // piggyback x(t+1) smem prefetch on this commit group
                        for (int ii = tid; ii < NR * 31; ii += NTHR) {
                            int r = ii / 31, cc = ii - r * 31;
                            cpasync4(smaddr(&inpS[r * 32 + cc]),
                                     &x[((size_t)(t + 1) * BATCH + (b0 + r)) * 31 + cc]);
                        }
                    }
                    issue_slab(sb + (uint32_t)((i + 3) & 3) * STAGE, kb_of(i + 3),
                               m0, tid, p);
                    cp_commit();
                }
                const uint32_t bufb = sb + (uint32_t)(i & 3) * STAGE;
                #pragma unroll
                for (int s4i = 0; s4i < 4; ++s4i) {
                    const int cur = s4i & 1;
                    const int pos = i * 4 + s4i;
                    if (pos < 63) {   // prefetch B for next (slab,s4) position
                        const int np = pos + 1;
                        const int kb2 = kb_of(np >> 2);
                        const int s42 = ((np & 3) + warp_n) & 3;
                        LOADB(bh[cur ^ 1], kb2, s42);
                    }
                    const int s4 = (s4i + warp_n) & 3;
                    #pragma unroll
                    for (int mf = 0; mf < 4; ++mf) {
                        uint32_t ah[4];
                        uint32_t aaddr = bufb
                            + (uint32_t)((aRowL + mf * 16) * 128)
                            + (uint32_t)((((2 * s4 + cA) ^ l7)) << 4);
                        ldmx4(ah, aaddr);
                        #pragma unroll
                        for (int nf = 0; nf < 8; ++nf)
                            mma16816(acc[mf][nf], ah,
                                     ((const uint32_t*)&bh[cur][nf >> 1]) + (nf & 1) * 2);
                    }
                }
            }

            // ---- register-resident LSTM epilogue ----
            #pragma unroll
            for (int mf = 0; mf < 4; ++mf) {
                #pragma unroll
                for (int e2 = 0; e2 < 2; ++e2) {
                    const int r  = warp_m * 64 + mf * 16 + e2 * 8 + lq;
                    const int rg = m0 + r;
                    const int e0 = e2 * 2;
                    float yp = 0.f;
                    #pragma unroll
                    for (int sub = 0; sub < 2; ++sub) {
                        const int jl = warp_n * 16 + sub * 8 + lc2;
                        float I0 = sigap(acc[mf][0 + sub][e0]     + biasS[jl]);
                        float I1 = sigap(acc[mf][0 + sub][e0 + 1] + biasS[jl + 1]);
                        float F0 = sigap(acc[mf][2 + sub][e0]     + biasS[64 + jl]);
                        float F1 = sigap(acc[mf][2 + sub][e0 + 1] + biasS[64 + jl + 1]);
                        float G0 = tanhap(acc[mf][4 + sub][e0]     + biasS[128 + jl]);
                        float G1 = tanhap(acc[mf][4 + sub][e0 + 1] + biasS[128 + jl + 1]);
                        float O0 = sigap(acc[mf][6 + sub][e0]     + biasS[192 + jl]);
                        float O1 = sigap(acc[mf][6 + sub][e0 + 1] + biasS[192 + jl + 1]);
                        float* cp = g_c + (size_t)rg * HID + hb * 64 + jl;
                        float2 cv = *(float2*)cp;
                        float cn0 = F0 * cv.x + I0 * G0;
                        float cn1 = F1 * cv.y + I1 * G1;
                        *(float2*)cp = make_float2(cn0, cn1);
                        float h0f = O0 * tanhap(cn0);
                        float h1f = O1 * tanhap(cn1);
                        const float2 wv = *(const float2*)(woutS + hb * 64 + jl);
                        yp = fmaf(h0f, wv.x, fmaf(h1f, wv.y, yp));
                        *(__half2*)(g_A + (size_t)rg * AKC + 512 + (p ^ 1) * 512
                                    + hb * 64 + jl) = __floats2half2_rn(h0f, h1f);
                    }
                    yp += __shfl_xor_sync(0xffffffffu, yp, 1);
                    yp += __shfl_xor_sync(0xffffffffu, yp, 2);
                    if ((lane & 3) == 0) atomicAdd(&ypartS[r], yp);
                }
            }
            __syncthreads();
            if (tid < 128) {
                g_ypart[(size_t)(m0 + tid) * 8 + hb] = ypartS[tid];
                ypartS[tid] = 0.f;
            }
        }

        grid_sync();   // h + ypart complete -> next row phase may read
    }
}

extern "C" void kernel_launch(void* const* d_in, const int* in_sizes, int n_in,
                              void* d_out, int out_size) {
    (void)in_sizes; (void)n_in; (void)out_size;
    const float* x     = (const float*)d_in[0];
    const float* h0    = (const float*)d_in[1];
    const float* c0    = (const float*)d_in[2];
    const float* y0    = (const float*)d_in[3];
    const float* W_in  = (const float*)d_in[4];
    const float* b_in  = (const float*)d_in[5];
    const float* W_ih  = (const float*)d_in[6];
    const float* W_hh  = (const float*)d_in[7];
    const float* b_ih  = (const float*)d_in[8];
    const float* b_hh  = (const float*)d_in[9];
    const float* W_out = (const float*)d_in[10];
    const float* b_out = (const float*)d_in[11];
    float* out = (float*)d_out;

    cudaFuncSetAttribute(lstm_persist, cudaFuncAttributeMaxDynamicSharedMemorySize, DYNSMEM);
    lstm_persist<<<NBLK, NTHR, DYNSMEM>>>(x, h0, c0, y0, W_in, b_in, W_ih, W_hh,
                                          b_ih, b_hh, W_out, b_out, out);
}